// round 1
// baseline (speedup 1.0000x reference)
#include <cuda_runtime.h>

typedef unsigned long long u64;

#define NCH_ 28          // input channels needed per cc-group: 4*4+12
#define XSP_ 33          // padded row pitch (bank-conflict free)
#define SMEM_WORDS (NCH_*32*XSP_ + 16*9*9*8)
#define SMEM_BYTES (SMEM_WORDS * 4)

__device__ __forceinline__ u64 pack2(float a, float b) {
    u64 r; asm("mov.b64 %0, {%1, %2};" : "=l"(r) : "f"(a), "f"(b)); return r;
}
__device__ __forceinline__ u64 fma2(u64 a, u64 b, u64 c) {
    u64 d; asm("fma.rn.f32x2 %0, %1, %2, %3;" : "=l"(d) : "l"(a), "l"(b), "l"(c)); return d;
}
__device__ __forceinline__ void unpack2(u64 v, float& lo, float& hi) {
    asm("mov.b64 {%0, %1}, %2;" : "=f"(lo), "=f"(hi) : "l"(v));
}

// out[b, n*32+cc, h, w] = sum_{c'<16, kh<9, kw<9}
//     x[b, (4cc-c')&127, (h-kh)&31, (w-kw)&31] * W[n, c', kh, kw]
// Block: one (b, group of 4 cc). 256 threads; each thread owns 2 adjacent w
// positions for one h, twice (2 chunks), all 8 n and all 4 cc of the group.
// Accumulators packed f32x2 over filter pairs (n, n+1).
__global__ __launch_bounds__(256, 1)
void fconv_kernel(const float* __restrict__ x,
                  const float* __restrict__ w,
                  float* __restrict__ out)
{
    extern __shared__ float smem[];
    float* xs  = smem;                   // [28][32][33]
    float* wsm = smem + NCH_ * 32 * XSP_; // [c'=16][kh=9][kw=9][n=8]

    const int t   = threadIdx.x;
    const int ccg = blockIdx.x;          // 0..7
    const int b   = blockIdx.y;          // 0..31
    const int cc0 = ccg * 4;
    const int ch_base = (4 * cc0 + 113) & 127;   // (4*cc0 - 15) mod 128

    // ---- stage x channels [ch_base .. ch_base+27] (mod 128) into smem ----
    const float* xb = x + (size_t)b * 128 * 1024;
    for (int idx = t; idx < NCH_ * 1024; idx += 256) {
        int ci = idx >> 10, p = idx & 1023;
        int cin = (ch_base + ci) & 127;
        xs[ci * (32 * XSP_) + (p >> 5) * XSP_ + (p & 31)] = xb[cin * 1024 + p];
    }
    // ---- stage weights transposed: wsm[((c*9+kh)*9+kw)*8 + n] ----
    for (int idx = t; idx < 16 * 81 * 8; idx += 256) {
        int n = idx & 7, r = idx >> 3;   // r = c*81 + kh*9 + kw
        wsm[idx] = w[n * 1296 + r];
    }
    __syncthreads();

    #pragma unroll 1
    for (int chunk = 0; chunk < 2; ++chunk) {
        const int p  = chunk * 512 + t * 2;
        const int h  = p >> 5;
        const int w0 = p & 31;           // even

        u64 acc[4][4][2];
        #pragma unroll
        for (int j = 0; j < 4; ++j)
            #pragma unroll
            for (int np = 0; np < 4; ++np) {
                acc[j][np][0] = 0ull; acc[j][np][1] = 0ull;
            }

        #pragma unroll 1
        for (int c = 0; c < 16; ++c) {
            #pragma unroll 1
            for (int kh = 0; kh < 9; ++kh) {
                const int hh = (h - kh) & 31;
                // hoist the 36 weight float2 (broadcast LDS.64) for this (c,kh)
                u64 wr[36];
                const float* wp = &wsm[(c * 9 + kh) * 72];
                #pragma unroll
                for (int q = 0; q < 36; ++q)
                    wr[q] = *(const u64*)(wp + q * 2);

                #pragma unroll
                for (int j = 0; j < 4; ++j) {
                    // cin = 4*(cc0+j) - c  ->  smem channel index 15 - c + 4j
                    const float* row =
                        &xs[(15 - c + 4 * j) * (32 * XSP_) + hh * XSP_];
                    // x window covering w0-8 .. w0+1 (circular)
                    u64 xp[10];
                    #pragma unroll
                    for (int i = 0; i < 10; ++i) {
                        float v = row[(w0 + 24 + i) & 31];
                        xp[i] = pack2(v, v);
                    }
                    #pragma unroll
                    for (int kw = 0; kw < 9; ++kw) {
                        #pragma unroll
                        for (int np = 0; np < 4; ++np) {
                            acc[j][np][0] = fma2(xp[8 - kw], wr[kw * 4 + np], acc[j][np][0]);
                            acc[j][np][1] = fma2(xp[9 - kw], wr[kw * 4 + np], acc[j][np][1]);
                        }
                    }
                }
            }
        }

        // ---- store: channel = n*32 + cc ----
        #pragma unroll
        for (int j = 0; j < 4; ++j) {
            const int cc = cc0 + j;
            #pragma unroll
            for (int np = 0; np < 4; ++np) {
                #pragma unroll
                for (int dw = 0; dw < 2; ++dw) {
                    float lo, hi;
                    unpack2(acc[j][np][dw], lo, hi);
                    size_t base = ((size_t)b * 256 + cc) * 1024 + h * 32 + w0 + dw;
                    out[base + (size_t)(2 * np)     * 32 * 1024] = lo;
                    out[base + (size_t)(2 * np + 1) * 32 * 1024] = hi;
                }
            }
        }
    }
}

extern "C" void kernel_launch(void* const* d_in, const int* in_sizes, int n_in,
                              void* d_out, int out_size)
{
    const float* x = (const float*)d_in[0];   // (32,128,32,32) f32
    const float* w = (const float*)d_in[1];   // (8,16,9,9) f32
    float* out = (float*)d_out;               // (32,256,32,32) f32

    cudaFuncSetAttribute(fconv_kernel,
                         cudaFuncAttributeMaxDynamicSharedMemorySize, SMEM_BYTES);
    dim3 grid(8, 32);
    fconv_kernel<<<grid, 256, SMEM_BYTES>>>(x, w, out);
}

// round 2
// speedup vs baseline: 1.0667x; 1.0667x over previous
#include <cuda_runtime.h>

typedef unsigned long long u64;

#define NCH_ 28            // input channels per cc-group: 4*4+12
#define XROW 40            // 8-word left halo + 32 words
#define XS_WORDS (NCH_ * 32 * XROW)          // 35840
#define W_WORDS  (16 * 9 * 9 * 8)            // 10368
#define SMEM_BYTES ((XS_WORDS + W_WORDS) * 4)  // 184832

__device__ __forceinline__ u64 pack2(float a, float b) {
    u64 r; asm("mov.b64 %0, {%1, %2};" : "=l"(r) : "f"(a), "f"(b)); return r;
}
__device__ __forceinline__ u64 fma2(u64 a, u64 b, u64 c) {
    u64 d; asm("fma.rn.f32x2 %0, %1, %2, %3;" : "=l"(d) : "l"(a), "l"(b), "l"(c)); return d;
}
__device__ __forceinline__ void unpack2(u64 v, float& lo, float& hi) {
    asm("mov.b64 {%0, %1}, %2;" : "=f"(lo), "=f"(hi) : "l"(v));
}

// out[b, n*32+cc, h, w] = sum_{c<16, kh<9, kw<9}
//     x[b, (4cc-c)&127, (h-kh)&31, (w-kw)&31] * W[n, c, kh, kw]
// Block: (b, group of 4 cc). 512 threads; each thread: one h, two w (w0,w0+1),
// all 8 n, 4 cc in two passes of 2 cc (register pressure).
__global__ __launch_bounds__(512, 1)
void fconv_kernel(const float* __restrict__ x,
                  const float* __restrict__ w,
                  float* __restrict__ out)
{
    extern __shared__ float smem[];
    float* xs  = smem;                 // [28][32][40] (halo rows)
    float* wsm = smem + XS_WORDS;      // [c=16][kh=9][kw=9][n=8]

    const int t   = threadIdx.x;
    const int ccg = blockIdx.x;        // 0..7
    const int b   = blockIdx.y;        // 0..31
    const int cc0 = ccg * 4;
    const int ch_base = (4 * cc0 + 113) & 127;    // (4*cc0 - 15) mod 128

    // ---- stage x (main body, coalesced) ----
    const float* xb = x + (size_t)b * 128 * 1024;
    for (int idx = t; idx < NCH_ * 1024; idx += 512) {
        int ci = idx >> 10, p = idx & 1023;
        int cin = (ch_base + ci) & 127;
        xs[ci * (32 * XROW) + (p >> 5) * XROW + 8 + (p & 31)] = xb[cin * 1024 + p];
    }
    // ---- stage x halo: rowbuf[k<8] = x[.., 24+k] ----
    for (int idx = t; idx < NCH_ * 32 * 8; idx += 512) {
        int ci = idx >> 8, r = idx & 255;
        int hh = r >> 3, k = r & 7;
        int cin = (ch_base + ci) & 127;
        xs[ci * (32 * XROW) + hh * XROW + k] = xb[cin * 1024 + hh * 32 + 24 + k];
    }
    // ---- stage weights transposed: wsm[((c*9+kh)*9+kw)*8 + n] ----
    for (int idx = t; idx < 16 * 81 * 8; idx += 512) {
        int n = idx & 7, r = idx >> 3;
        wsm[idx] = w[n * 1296 + r];
    }
    __syncthreads();

    // thread mapping: half-warp shares h (conflict-free LDS.64 / coalesced STG)
    const int lane = t & 31;
    const int wp   = t >> 5;
    const int h    = wp * 2 + (lane >> 4);
    const int w0   = (lane & 15) * 2;

    #pragma unroll 1
    for (int jp = 0; jp < 4; jp += 2) {
        u64 acc[2][4][2];
        #pragma unroll
        for (int dj = 0; dj < 2; ++dj)
            #pragma unroll
            for (int np = 0; np < 4; ++np) {
                acc[dj][np][0] = 0ull; acc[dj][np][1] = 0ull;
            }

        #pragma unroll 1
        for (int c = 0; c < 16; ++c) {
            #pragma unroll 1
            for (int kh = 0; kh < 9; ++kh) {
                const int hh = (h - kh) & 31;

                // hoist 36 weight pairs via 18 LDS.128
                u64 wr[36];
                const ulonglong2* wp2 =
                    (const ulonglong2*)&wsm[(c * 9 + kh) * 72];
                #pragma unroll
                for (int q = 0; q < 18; ++q) {
                    ulonglong2 v = wp2[q];
                    wr[2 * q] = v.x; wr[2 * q + 1] = v.y;
                }

                #pragma unroll
                for (int dj = 0; dj < 2; ++dj) {
                    const int j = jp + dj;
                    const float* row =
                        &xs[(15 - c + 4 * j) * (32 * XROW) + hh * XROW + w0];
                    // xp[i] = x[(w0 - 8 + i) & 31], i = 0..9, via 5 LDS.64
                    u64 xp[10];
                    #pragma unroll
                    for (int q = 0; q < 5; ++q) {
                        u64 raw = *(const u64*)(row + 2 * q);
                        float lo, hi; unpack2(raw, lo, hi);
                        xp[2 * q]     = pack2(lo, lo);
                        xp[2 * q + 1] = pack2(hi, hi);
                    }
                    #pragma unroll
                    for (int kw = 0; kw < 9; ++kw) {
                        #pragma unroll
                        for (int np = 0; np < 4; ++np) {
                            acc[dj][np][0] = fma2(xp[8 - kw], wr[kw * 4 + np], acc[dj][np][0]);
                            acc[dj][np][1] = fma2(xp[9 - kw], wr[kw * 4 + np], acc[dj][np][1]);
                        }
                    }
                }
            }
        }

        // ---- store: channel = n*32 + cc, float2 over (w0, w0+1) ----
        #pragma unroll
        for (int dj = 0; dj < 2; ++dj) {
            const int cc = cc0 + jp + dj;
            #pragma unroll
            for (int np = 0; np < 4; ++np) {
                float a0n0, a0n1, a1n0, a1n1;
                unpack2(acc[dj][np][0], a0n0, a0n1);   // w0:   n=2np, 2np+1
                unpack2(acc[dj][np][1], a1n0, a1n1);   // w0+1: n=2np, 2np+1
                size_t base = ((size_t)b * 256 + cc) * 1024 + h * 32 + w0;
                float2 s0 = make_float2(a0n0, a1n0);
                float2 s1 = make_float2(a0n1, a1n1);
                *(float2*)&out[base + (size_t)(2 * np)     * 32 * 1024] = s0;
                *(float2*)&out[base + (size_t)(2 * np + 1) * 32 * 1024] = s1;
            }
        }
    }
}

extern "C" void kernel_launch(void* const* d_in, const int* in_sizes, int n_in,
                              void* d_out, int out_size)
{
    const float* x = (const float*)d_in[0];   // (32,128,32,32) f32
    const float* w = (const float*)d_in[1];   // (8,16,9,9) f32
    float* out = (float*)d_out;               // (32,256,32,32) f32

    cudaFuncSetAttribute(fconv_kernel,
                         cudaFuncAttributeMaxDynamicSharedMemorySize, SMEM_BYTES);
    dim3 grid(8, 32);
    fconv_kernel<<<grid, 512, SMEM_BYTES>>>(x, w, out);
}